// round 3
// baseline (speedup 1.0000x reference)
#include <cuda_runtime.h>
#include <math.h>

#define NFFT 5000
#define NFULL 10000
#define NROWS (256*20)          // 5120 FFT rows
#define FFT_THREADS 256
#define FFT_SMEM (4*NFFT*4)     // 80000 bytes: re0,im0,re1,im1

#define PAD_A 108               // 108 % 32 = 12 -> conflict-free float4 lane pattern
#define PAD_W 104
#define GEMM_ROWS 128           // batch rows per block (2 blocks per segment)
#define GEMM_SMEM ((GEMM_ROWS*PAD_A + 32*PAD_W)*4)   // 68608 bytes

// ---------------- scratch (no allocations allowed) ----------------
__device__ float2 d_wtab[NFFT];                 // exp(-2*pi*i*k/5000)
__device__ float  d_xl[(size_t)256*20*10000];   // log|FFT(x)|, layout [b][c][j]
__device__ float  d_x2[(size_t)256*32*100];     // relu(conv1), layout [b][o][s]

// ---------------- twiddle table ----------------
__global__ void twiddle_kernel() {
    int k = blockIdx.x * blockDim.x + threadIdx.x;
    if (k < NFFT) {
        double ang = -2.0 * 3.14159265358979323846 * (double)k / (double)NFFT;
        d_wtab[k] = make_float2((float)cos(ang), (float)sin(ang));
    }
}

// ---------------- FFT helpers ----------------
__device__ __forceinline__ float2 cmulf(float2 a, float2 b) {
    return make_float2(a.x*b.x - a.y*b.y, a.x*b.y + a.y*b.x);
}

template<int NS>
__device__ __forceinline__ void radix5_stage(const float* __restrict__ ra, const float* __restrict__ ia,
                                             float* __restrict__ rb, float* __restrict__ ib, int tid) {
    const int STEP = NFFT / (NS * 5);
    for (int j = tid; j < NFFT/5; j += FFT_THREADS) {
        const int m = j % NS;
        const int t = m * STEP;
        float2 w1 = d_wtab[t];
        float2 w2 = d_wtab[2*t];
        float2 w3 = d_wtab[3*t];
        float2 w4 = d_wtab[4*t];
        float2 x0 = make_float2(ra[j],        ia[j]);
        float2 x1 = cmulf(make_float2(ra[j+1000], ia[j+1000]), w1);
        float2 x2 = cmulf(make_float2(ra[j+2000], ia[j+2000]), w2);
        float2 x3 = cmulf(make_float2(ra[j+3000], ia[j+3000]), w3);
        float2 x4 = cmulf(make_float2(ra[j+4000], ia[j+4000]), w4);
        float t1r = x1.x + x4.x, t1i = x1.y + x4.y;
        float t2r = x2.x + x3.x, t2i = x2.y + x3.y;
        float t3r = x1.x - x4.x, t3i = x1.y - x4.y;
        float t4r = x2.x - x3.x, t4i = x2.y - x3.y;
        const float c1 =  0.309016994374947424f;   // cos(2pi/5)
        const float c2 = -0.809016994374947424f;   // cos(4pi/5)
        const float s1 =  0.951056516295153572f;   // sin(2pi/5)
        const float s2 =  0.587785252292473129f;   // sin(4pi/5)
        float y0r = x0.x + t1r + t2r, y0i = x0.y + t1i + t2i;
        float par = x0.x + c1*t1r + c2*t2r, pai = x0.y + c1*t1i + c2*t2i;
        float pbr = s1*t3r + s2*t4r,        pbi = s1*t3i + s2*t4i;
        float pcr = x0.x + c2*t1r + c1*t2r, pci = x0.y + c2*t1i + c1*t2i;
        float pdr = s2*t3r - s1*t4r,        pdi = s2*t3i - s1*t4i;
        const int d = (j / NS) * (NS*5) + m;
        rb[d]        = y0r;       ib[d]        = y0i;
        rb[d +   NS] = par + pbi; ib[d +   NS] = pai - pbr;   // X1 = P - iQ
        rb[d + 2*NS] = pcr + pdi; ib[d + 2*NS] = pci - pdr;   // X2
        rb[d + 3*NS] = pcr - pdi; ib[d + 3*NS] = pci + pdr;   // X3
        rb[d + 4*NS] = par - pbi; ib[d + 4*NS] = pai + pbr;   // X4
    }
}

__device__ __forceinline__ void radix4_stage(const float* __restrict__ ra, const float* __restrict__ ia,
                                             float* __restrict__ rb, float* __restrict__ ib, int tid) {
    // NS = 625, R = 4, STEP = 5000/(625*4) = 2
    for (int j = tid; j < 1250; j += FFT_THREADS) {
        const int m = j % 625;
        const int t = 2 * m;
        float2 w1 = d_wtab[t];
        float2 w2 = d_wtab[2*t];
        float2 w3 = d_wtab[3*t];
        float2 x0 = make_float2(ra[j],        ia[j]);
        float2 x1 = cmulf(make_float2(ra[j+1250], ia[j+1250]), w1);
        float2 x2 = cmulf(make_float2(ra[j+2500], ia[j+2500]), w2);
        float2 x3 = cmulf(make_float2(ra[j+3750], ia[j+3750]), w3);
        float t0r = x0.x + x2.x, t0i = x0.y + x2.y;
        float t1r = x0.x - x2.x, t1i = x0.y - x2.y;
        float t2r = x1.x + x3.x, t2i = x1.y + x3.y;
        float t3r = x1.x - x3.x, t3i = x1.y - x3.y;
        const int d = (j / 625) * 2500 + m;
        rb[d]        = t0r + t2r; ib[d]        = t0i + t2i;   // X0
        rb[d +  625] = t1r + t3i; ib[d +  625] = t1i - t3r;   // X1 = t1 - i*t3
        rb[d + 1250] = t0r - t2r; ib[d + 1250] = t0i - t2i;   // X2
        rb[d + 1875] = t1r - t3i; ib[d + 1875] = t1i + t3r;   // X3
    }
}

__device__ __forceinline__ void radix2_stage(const float* __restrict__ ra, const float* __restrict__ ia,
                                             float* __restrict__ rb, float* __restrict__ ib, int tid) {
    // NS = 2500, R = 2, STEP = 1
    for (int j = tid; j < 2500; j += FFT_THREADS) {
        float2 w = d_wtab[j];
        float2 a = make_float2(ra[j],        ia[j]);
        float2 b = cmulf(make_float2(ra[j+2500], ia[j+2500]), w);
        rb[j]        = a.x + b.x; ib[j]        = a.y + b.y;
        rb[j + 2500] = a.x - b.x; ib[j + 2500] = a.y - b.y;
    }
}

// ---------------- Pass 1: per-row real FFT (length 10000 via 5000-pack) + log|.| ----------------
__global__ __launch_bounds__(FFT_THREADS, 2)
void fft_logabs_kernel(const float* __restrict__ x) {
    extern __shared__ float sm[];
    float* re0 = sm;
    float* im0 = sm + NFFT;
    float* re1 = sm + 2*NFFT;
    float* im1 = sm + 3*NFFT;
    const int tid = threadIdx.x;
    const size_t row = blockIdx.x;

    // pack: z[n] = x[2n] + i*x[2n+1]
    const float2* xin = (const float2*)(x + row * NFULL);
    for (int n = tid; n < NFFT; n += FFT_THREADS) {
        float2 v = xin[n];
        re0[n] = v.x; im0[n] = v.y;
    }
    __syncthreads();

    radix5_stage<1>  (re0, im0, re1, im1, tid); __syncthreads();
    radix5_stage<5>  (re1, im1, re0, im0, tid); __syncthreads();
    radix5_stage<25> (re0, im0, re1, im1, tid); __syncthreads();
    radix5_stage<125>(re1, im1, re0, im0, tid); __syncthreads();
    radix4_stage     (re0, im0, re1, im1, tid); __syncthreads();
    radix2_stage     (re1, im1, re0, im0, tid); __syncthreads();
    // result Z[k] in (re0, im0)

    float* outp = d_xl + row * NFULL;
    for (int k = tid; k <= 2500; k += FFT_THREADS) {
        const int km = (k == 0) ? 0 : (NFFT - k);
        float ar = re0[k],  ai = im0[k];
        float br = re0[km], bi = im0[km];
        // E = (Z[k] + conj(Z[-k]))/2 ; O = (Z[k] - conj(Z[-k]))/(2i)
        float Er = 0.5f*(ar + br), Ei = 0.5f*(ai - bi);
        float Or = 0.5f*(ai + bi), Oi = 0.5f*(br - ar);
        // W = exp(-2*pi*i*k/10000) = exp(-i*pi*k/5000)
        float s, c;
        sincospif(-(float)k * (1.0f/5000.0f), &s, &c);
        float tr = c*Or - s*Oi;
        float ti = c*Oi + s*Or;
        float pr = Er + tr, pi = Ei + ti;   // X[k]
        float mr = Er - tr, mi = Ei - ti;   // X[k+5000]; |X[5000+k]| == |X[5000-k]|
        float l1 = 0.5f * logf(pr*pr + pi*pi);
        float l2 = 0.5f * logf(mr*mr + mi*mi);
        outp[k]        = l1;
        outp[5000 - k] = l2;
        if (k > 0) {
            outp[10000 - k] = l1;   // conj symmetry of real-input FFT
            outp[5000 + k]  = l2;
        }
    }
}

// ---------------- Pass 2: per-segment GEMM ----------------
// x2[b,o,s] = relu( sum_{c,k} xl[b,c,s*100+k] * W1[s,o,c,k] + b1[s,o] )
// Grid: 200 blocks = (segment s) x (batch half). Each block: 128 b-rows, all 32 o.
__global__ __launch_bounds__(256, 2)
void seg_gemm_kernel(const float* __restrict__ W1, const float* __restrict__ b1) {
    extern __shared__ float sm[];
    float* Asm = sm;                        // [128][PAD_A] (100 valid k)
    float* Wsm = sm + GEMM_ROWS * PAD_A;    // [32][PAD_W]
    const int s    = blockIdx.x >> 1;
    const int b0   = (blockIdx.x & 1) * GEMM_ROWS;
    const int tid  = threadIdx.x;
    const int bg   = tid & 31;              // b lane (local b = bg + 32*i, i<4)
    const int og   = tid >> 5;              // 0..7
    const int o0   = og * 4;

    float acc[4][4];
    #pragma unroll
    for (int i = 0; i < 4; i++)
        #pragma unroll
        for (int j = 0; j < 4; j++) acc[i][j] = 0.0f;

    for (int c = 0; c < 20; c++) {
        // load A tile: 128 b-rows x 100 k floats (float4, coalesced)
        for (int q = tid; q < GEMM_ROWS*25; q += 256) {
            int b  = q / 25;
            int kq = q % 25;
            float4 v = *(const float4*)(d_xl + ((size_t)(b0 + b)*20 + c)*10000 + s*100 + kq*4);
            *(float4*)(Asm + b*PAD_A + kq*4) = v;
        }
        // load W tile: 32 o-rows x 100 k floats
        for (int q = tid; q < 800; q += 256) {
            int o  = q / 25;
            int kq = q % 25;
            float4 v = *(const float4*)(W1 + (((size_t)s*32 + o)*20 + c)*100 + kq*4);
            *(float4*)(Wsm + o*PAD_W + kq*4) = v;
        }
        __syncthreads();

        for (int k = 0; k < 100; k += 4) {
            float4 wv[4];
            #pragma unroll
            for (int j = 0; j < 4; j++)
                wv[j] = *(const float4*)(Wsm + (o0 + j)*PAD_W + k);
            float4 av[4];
            #pragma unroll
            for (int i = 0; i < 4; i++)
                av[i] = *(const float4*)(Asm + (bg + 32*i)*PAD_A + k);
            #pragma unroll
            for (int i = 0; i < 4; i++)
                #pragma unroll
                for (int j = 0; j < 4; j++) {
                    acc[i][j] += av[i].x * wv[j].x;
                    acc[i][j] += av[i].y * wv[j].y;
                    acc[i][j] += av[i].z * wv[j].z;
                    acc[i][j] += av[i].w * wv[j].w;
                }
        }
        __syncthreads();
    }

    #pragma unroll
    for (int i = 0; i < 4; i++) {
        int b = b0 + bg + 32*i;
        #pragma unroll
        for (int j = 0; j < 4; j++) {
            int o = o0 + j;
            float v = acc[i][j] + b1[s*32 + o];
            d_x2[((size_t)b*32 + o)*100 + s] = fmaxf(v, 0.0f);
        }
    }
}

// ---------------- Pass 3: out[b,j] = relu(sum_i x2[b][i] * W2[j][i] + b2[j]) ----------------
__global__ __launch_bounds__(128)
void final_kernel(const float* __restrict__ W2, const float* __restrict__ b2,
                  float* __restrict__ out) {
    const int b   = blockIdx.x;
    const int tid = threadIdx.x;
    float acc[6] = {0.f, 0.f, 0.f, 0.f, 0.f, 0.f};
    const float* xb = d_x2 + (size_t)b * 3200;
    for (int i = tid; i < 3200; i += 128) {
        float v = xb[i];
        #pragma unroll
        for (int j = 0; j < 6; j++) acc[j] += v * W2[j*3200 + i];
    }
    #pragma unroll
    for (int off = 16; off > 0; off >>= 1)
        #pragma unroll
        for (int j = 0; j < 6; j++)
            acc[j] += __shfl_xor_sync(0xFFFFFFFFu, acc[j], off);
    __shared__ float red[4][6];
    if ((tid & 31) == 0) {
        #pragma unroll
        for (int j = 0; j < 6; j++) red[tid >> 5][j] = acc[j];
    }
    __syncthreads();
    if (tid < 6) {
        float t = red[0][tid] + red[1][tid] + red[2][tid] + red[3][tid] + b2[tid];
        out[b*6 + tid] = fmaxf(t, 0.0f);
    }
}

// ---------------- launch ----------------
extern "C" void kernel_launch(void* const* d_in, const int* in_sizes, int n_in,
                              void* d_out, int out_size) {
    (void)in_sizes; (void)n_in; (void)out_size;
    const float* x  = (const float*)d_in[0];
    const float* W1 = (const float*)d_in[1];
    const float* b1 = (const float*)d_in[2];
    const float* W2 = (const float*)d_in[3];
    const float* b2 = (const float*)d_in[4];
    float* out = (float*)d_out;

    cudaFuncSetAttribute(fft_logabs_kernel, cudaFuncAttributeMaxDynamicSharedMemorySize, FFT_SMEM);
    cudaFuncSetAttribute(seg_gemm_kernel,   cudaFuncAttributeMaxDynamicSharedMemorySize, GEMM_SMEM);

    twiddle_kernel<<<20, 256>>>();
    fft_logabs_kernel<<<NROWS, FFT_THREADS, FFT_SMEM>>>(x);
    seg_gemm_kernel<<<200, 256, GEMM_SMEM>>>(W1, b1);
    final_kernel<<<256, 128>>>(W2, b2, out);
}